// round 1
// baseline (speedup 1.0000x reference)
#include <cuda_runtime.h>

#define B_   8
#define C_   64
#define H_   128
#define W_   128
#define CE_  576
#define P_   (H_*W_)
#define OUP_ 128
#define KT_  576
#define EPSF 1e-5f

// Scratch (device globals: no runtime allocation allowed)
__device__ float g_a[(size_t)B_*CE_*P_];   // 302 MB: relu(bn(dwconv)) in [b][ce][h][w]
__device__ float g_stats[B_*C_*2];         // sum, sumsq per (b,c)
__device__ float g_gate[B_*C_*4];          // gCw, alpha, beta, (1-wadd)
__device__ float g_wt[KT_*OUP_];           // conv_w transposed: [k][o]
__device__ float g_ep[OUP_*2];             // conv BN folded: scale, shift per o

// ---------------- k0: zero stats ----------------
__global__ void k0_zero() { g_stats[threadIdx.x] = 0.f; }

// ---------------- k1: depthwise conv + BN + ReLU + stats ----------------
__global__ __launch_bounds__(256) void k1_gen(
    const float* __restrict__ x,  const float* __restrict__ gw,
    const float* __restrict__ bg, const float* __restrict__ bb,
    const float* __restrict__ bm, const float* __restrict__ bv)
{
    int t = threadIdx.x;
    int rowblk = blockIdx.x, c = blockIdx.y, b = blockIdx.z;
    __shared__ float sx[18*130];
    __shared__ float swv[81], ssc[9], ssh[9];
    __shared__ float red[16];

    const float* xp = x + (size_t)(b*C_ + c)*P_;
    for (int idx = t; idx < 18*130; idx += 256) {
        int rr = idx / 130, cc = idx - rr*130;
        int gh = rowblk*16 + rr - 1, gwc = cc - 1;
        float v = 0.f;
        if ((unsigned)gh < (unsigned)H_ && (unsigned)gwc < (unsigned)W_)
            v = xp[gh*W_ + gwc];
        sx[idx] = v;
    }
    int ce0 = c*9;
    if (t < 81) swv[t] = gw[ce0*9 + t];
    if (t < 9) {
        float g = bg[ce0+t];
        float sc = g / sqrtf(bv[ce0+t] + EPSF);
        ssc[t] = sc;
        ssh[t] = bb[ce0+t] - bm[ce0+t]*sc;
    }
    __syncthreads();

    int r = t >> 4, c8 = (t & 15) * 8;
    float xs0[10], xs1[10], xs2[10];
    #pragma unroll
    for (int i = 0; i < 10; i++) {
        xs0[i] = sx[(r  )*130 + c8 + i];
        xs1[i] = sx[(r+1)*130 + c8 + i];
        xs2[i] = sx[(r+2)*130 + c8 + i];
    }
    float lsum = 0.f, lsq = 0.f;
    int gh0 = rowblk*16 + r;
    #pragma unroll
    for (int j = 0; j < 9; j++) {
        float w0=swv[j*9+0], w1=swv[j*9+1], w2=swv[j*9+2];
        float w3=swv[j*9+3], w4=swv[j*9+4], w5=swv[j*9+5];
        float w6=swv[j*9+6], w7=swv[j*9+7], w8=swv[j*9+8];
        float sc = ssc[j], sh = ssh[j];
        float v[8];
        #pragma unroll
        for (int px = 0; px < 8; px++) {
            float acc = xs0[px]*w0;
            acc = fmaf(xs0[px+1], w1, acc);
            acc = fmaf(xs0[px+2], w2, acc);
            acc = fmaf(xs1[px  ], w3, acc);
            acc = fmaf(xs1[px+1], w4, acc);
            acc = fmaf(xs1[px+2], w5, acc);
            acc = fmaf(xs2[px  ], w6, acc);
            acc = fmaf(xs2[px+1], w7, acc);
            acc = fmaf(xs2[px+2], w8, acc);
            float av = fmaxf(fmaf(acc, sc, sh), 0.f);
            v[px] = av;
            lsum += av;
            lsq = fmaf(av, av, lsq);
        }
        float* op = g_a + ((size_t)(b*CE_ + ce0 + j)*H_ + gh0)*W_ + c8;
        *reinterpret_cast<float4*>(op)   = make_float4(v[0], v[1], v[2], v[3]);
        *reinterpret_cast<float4*>(op+4) = make_float4(v[4], v[5], v[6], v[7]);
    }
    // block reduction -> atomics
    #pragma unroll
    for (int off = 16; off; off >>= 1) {
        lsum += __shfl_down_sync(0xffffffffu, lsum, off);
        lsq  += __shfl_down_sync(0xffffffffu, lsq , off);
    }
    int wid = t >> 5, lane = t & 31;
    if (lane == 0) { red[wid] = lsum; red[wid+8] = lsq; }
    __syncthreads();
    if (t == 0) {
        float s = 0.f, q = 0.f;
        #pragma unroll
        for (int i = 0; i < 8; i++) { s += red[i]; q += red[i+8]; }
        atomicAdd(&g_stats[(b*C_+c)*2+0], s);
        atomicAdd(&g_stats[(b*C_+c)*2+1], q);
    }
}

// ---------------- k2: fold gate params ----------------
__global__ void k2_gate(const float* __restrict__ gn_w, const float* __restrict__ gn_b,
    const float* __restrict__ cw, const float* __restrict__ cb,
    const float* __restrict__ sw, const float* __restrict__ sb,
    const float* __restrict__ wadd_p)
{
    int t = threadIdx.x;
    if (t >= B_*C_) return;
    int c = t & (C_-1), cg = c & 7;
    float s = g_stats[t*2], q = g_stats[t*2+1];
    const float N = (float)(9*P_);
    float mean = s / N;
    float var  = fmaxf(q / N - mean*mean, 0.f);
    float inv  = 1.f / sqrtf(var + EPSF);
    float wadd = *wadd_p;
    float tc = cw[cg]*mean + cb[cg];
    float gC = 1.f / (1.f + __expf(-tc));
    float alpha = sw[cg]*gn_w[cg]*inv;
    float beta  = sw[cg]*(gn_b[cg] - mean*inv*gn_w[cg]) + sb[cg];
    g_gate[t*4+0] = wadd*gC;
    g_gate[t*4+1] = alpha;
    g_gate[t*4+2] = beta;
    g_gate[t*4+3] = 1.f - wadd;
}

// ---------------- k2b: transpose W, fold conv BN ----------------
__global__ void k2b_prep(const float* __restrict__ cwv,
    const float* __restrict__ g, const float* __restrict__ bb,
    const float* __restrict__ m, const float* __restrict__ v)
{
    int idx = blockIdx.x*256 + threadIdx.x;
    if (idx < KT_*OUP_) {
        int k = idx >> 7, o = idx & 127;
        g_wt[idx] = cwv[o*KT_ + k];
    }
    if (idx < OUP_) {
        float sc = g[idx] / sqrtf(v[idx] + EPSF);
        g_ep[idx*2]   = sc;
        g_ep[idx*2+1] = bb[idx] - m[idx]*sc;
    }
}

// ---------------- k3: fused gate + GEMM(128 x 131072 x 576) + BN + SiLU ----------------
#define FMA2(d,a,b) asm("fma.rn.f32x2 %0, %1, %2, %0;" : "+l"(d) : "l"(a), "l"(b))
#define PK2(d,s)    asm("mov.b64 %0, {%1, %1};" : "=l"(d) : "f"(s))

__global__ __launch_bounds__(256, 2) void k3_conv(float* __restrict__ out)
{
    int t = threadIdx.x;
    int tx = t & 15, ty = t >> 4;
    int pos0 = blockIdx.x * 128;
    int b = blockIdx.y;
    __shared__ __align__(16) float Ws[16*128];
    __shared__ __align__(16) float As[16*128];
    __shared__ float gp[256];
    if (t < 256) gp[t] = g_gate[b*256 + t];

    unsigned long long acc[8][4];
    #pragma unroll
    for (int i = 0; i < 8; i++)
        #pragma unroll
        for (int p = 0; p < 4; p++) acc[i][p] = 0ull;

    const float* aBase = g_a + (size_t)b*CE_*P_ + pos0;
    int kkA = t >> 4;
    int pxA = (t & 15) * 8;

    for (int kc = 0; kc < 36; kc++) {
        __syncthreads();
        // load W chunk [16k x 128o] (already transposed to [k][o] in gmem)
        const float* wp = g_wt + kc*16*128;
        float4 wv0 = reinterpret_cast<const float4*>(wp)[t*2];
        float4 wv1 = reinterpret_cast<const float4*>(wp)[t*2+1];
        *reinterpret_cast<float4*>(&Ws[t*8])   = wv0;
        *reinterpret_cast<float4*>(&Ws[t*8+4]) = wv1;
        // load A chunk + gate transform
        int kglob = kc*16 + kkA;
        const float* ap = aBase + (size_t)kglob*P_ + pxA;
        float4 a0 = *reinterpret_cast<const float4*>(ap);
        float4 a1 = *reinterpret_cast<const float4*>(ap+4);
        int crow = kglob / 9;
        float gCw = gp[crow*4+0], al = gp[crow*4+1];
        float be  = gp[crow*4+2], w2 = gp[crow*4+3];
        float av[8] = {a0.x,a0.y,a0.z,a0.w,a1.x,a1.y,a1.z,a1.w};
        #pragma unroll
        for (int i = 0; i < 8; i++) {
            float a_ = av[i];
            float sg = 1.f / (1.f + __expf(-fmaf(al, a_, be)));
            av[i] = a_ * fmaf(w2, sg, gCw);
        }
        *reinterpret_cast<float4*>(&As[kkA*128+pxA])   = make_float4(av[0],av[1],av[2],av[3]);
        *reinterpret_cast<float4*>(&As[kkA*128+pxA+4]) = make_float4(av[4],av[5],av[6],av[7]);
        __syncthreads();

        #pragma unroll
        for (int kk = 0; kk < 16; kk++) {
            float4 wa  = *reinterpret_cast<const float4*>(&Ws[kk*128 + ty*8]);
            float4 wb  = *reinterpret_cast<const float4*>(&Ws[kk*128 + ty*8 + 4]);
            unsigned long long wp2[8];
            PK2(wp2[0], wa.x); PK2(wp2[1], wa.y); PK2(wp2[2], wa.z); PK2(wp2[3], wa.w);
            PK2(wp2[4], wb.x); PK2(wp2[5], wb.y); PK2(wp2[6], wb.z); PK2(wp2[7], wb.w);
            const double* arow = reinterpret_cast<const double*>(&As[kk*128]);
            #pragma unroll
            for (int pp = 0; pp < 4; pp++) {
                unsigned long long a2 = __double_as_longlong(arow[tx + 16*pp]);
                #pragma unroll
                for (int oo = 0; oo < 8; oo++) FMA2(acc[oo][pp], a2, wp2[oo]);
            }
        }
    }
    // epilogue: BN + SiLU, write out
    #pragma unroll
    for (int oo = 0; oo < 8; oo++) {
        int o = ty*8 + oo;
        float sc = g_ep[o*2], sh = g_ep[o*2+1];
        float* op = out + ((size_t)b*OUP_ + o)*P_ + pos0;
        #pragma unroll
        for (int pp = 0; pp < 4; pp++) {
            uint2 u = *reinterpret_cast<uint2*>(&acc[oo][pp]);
            float z0 = fmaf(__uint_as_float(u.x), sc, sh);
            float z1 = fmaf(__uint_as_float(u.y), sc, sh);
            float r0 = z0 / (1.f + __expf(-z0));
            float r1 = z1 / (1.f + __expf(-z1));
            int pos = 2*(tx + 16*pp);
            *reinterpret_cast<float2*>(op + pos) = make_float2(r0, r1);
        }
    }
}

extern "C" void kernel_launch(void* const* d_in, const int* in_sizes, int n_in,
                              void* d_out, int out_size)
{
    const float* x      = (const float*)d_in[0];
    const float* gen_w  = (const float*)d_in[1];
    const float* bg     = (const float*)d_in[2];
    const float* bb     = (const float*)d_in[3];
    const float* bm     = (const float*)d_in[4];
    const float* bv     = (const float*)d_in[5];
    const float* gn_w   = (const float*)d_in[6];
    const float* gn_b   = (const float*)d_in[7];
    const float* cw     = (const float*)d_in[8];
    const float* cb     = (const float*)d_in[9];
    const float* sw     = (const float*)d_in[10];
    const float* sb     = (const float*)d_in[11];
    const float* wadd   = (const float*)d_in[12];
    const float* conv_w = (const float*)d_in[13];
    const float* cbg    = (const float*)d_in[14];
    const float* cbb    = (const float*)d_in[15];
    const float* cbm    = (const float*)d_in[16];
    const float* cbv    = (const float*)d_in[17];
    float* out = (float*)d_out;

    k0_zero<<<1, 1024>>>();
    k1_gen<<<dim3(8, C_, B_), 256>>>(x, gen_w, bg, bb, bm, bv);
    k2_gate<<<1, 512>>>(gn_w, gn_b, cw, cb, sw, sb, wadd);
    k2b_prep<<<(KT_*OUP_ + 255)/256, 256>>>(conv_w, cbg, cbb, cbm, cbv);
    k3_conv<<<dim3(P_/128, B_), 256>>>(out);
}

// round 3
// speedup vs baseline: 1.3912x; 1.3912x over previous
#include <cuda_runtime.h>
#include <cstdint>

#define B_   8
#define C_   64
#define H_   128
#define W_   128
#define CE_  576
#define P_   (H_*W_)
#define OUP_ 128
#define EPSF 1e-5f

// ---- scratch (device globals; no runtime allocation allowed) ----
__device__ float g_a[(size_t)B_*CE_*P_];   // 302 MB: relu(bn(dwconv))  [b][k][p]
__device__ float g_stats[B_*C_*2];         // sum, sumsq per (b,c)
__device__ float g_gate[B_*C_*4];          // G0, G1, A1, B1 per (b,c)
__device__ float g_ep[OUP_*2];             // conv BN folded: scale, shift per o

// ---------------- k0: zero stats ----------------
__global__ void k0_zero() { g_stats[threadIdx.x] = 0.f; }

// ---------------- k1: depthwise conv + BN + ReLU + stats ----------------
__global__ __launch_bounds__(256) void k1_gen(
    const float* __restrict__ x,  const float* __restrict__ gw,
    const float* __restrict__ bg, const float* __restrict__ bb,
    const float* __restrict__ bm, const float* __restrict__ bv)
{
    int t = threadIdx.x;
    int rowblk = blockIdx.x, c = blockIdx.y, b = blockIdx.z;
    __shared__ float sx[18*130];
    __shared__ float swv[81], ssc[9], ssh[9];
    __shared__ float red[16];

    const float* xp = x + (size_t)(b*C_ + c)*P_;
    for (int idx = t; idx < 18*130; idx += 256) {
        int rr = idx / 130, cc = idx - rr*130;
        int gh = rowblk*16 + rr - 1, gwc = cc - 1;
        float v = 0.f;
        if ((unsigned)gh < (unsigned)H_ && (unsigned)gwc < (unsigned)W_)
            v = xp[gh*W_ + gwc];
        sx[idx] = v;
    }
    int ce0 = c*9;
    if (t < 81) swv[t] = gw[ce0*9 + t];
    if (t < 9) {
        float g = bg[ce0+t];
        float sc = g / sqrtf(bv[ce0+t] + EPSF);
        ssc[t] = sc;
        ssh[t] = bb[ce0+t] - bm[ce0+t]*sc;
    }
    __syncthreads();

    int r = t >> 4, c8 = (t & 15) * 8;
    float xs0[10], xs1[10], xs2[10];
    #pragma unroll
    for (int i = 0; i < 10; i++) {
        xs0[i] = sx[(r  )*130 + c8 + i];
        xs1[i] = sx[(r+1)*130 + c8 + i];
        xs2[i] = sx[(r+2)*130 + c8 + i];
    }
    float lsum = 0.f, lsq = 0.f;
    int gh0 = rowblk*16 + r;
    #pragma unroll
    for (int j = 0; j < 9; j++) {
        float w0=swv[j*9+0], w1=swv[j*9+1], w2=swv[j*9+2];
        float w3=swv[j*9+3], w4=swv[j*9+4], w5=swv[j*9+5];
        float w6=swv[j*9+6], w7=swv[j*9+7], w8=swv[j*9+8];
        float sc = ssc[j], sh = ssh[j];
        float v[8];
        #pragma unroll
        for (int px = 0; px < 8; px++) {
            float acc = xs0[px]*w0;
            acc = fmaf(xs0[px+1], w1, acc);
            acc = fmaf(xs0[px+2], w2, acc);
            acc = fmaf(xs1[px  ], w3, acc);
            acc = fmaf(xs1[px+1], w4, acc);
            acc = fmaf(xs1[px+2], w5, acc);
            acc = fmaf(xs2[px  ], w6, acc);
            acc = fmaf(xs2[px+1], w7, acc);
            acc = fmaf(xs2[px+2], w8, acc);
            float av = fmaxf(fmaf(acc, sc, sh), 0.f);
            v[px] = av;
            lsum += av;
            lsq = fmaf(av, av, lsq);
        }
        float* op = g_a + ((size_t)(b*CE_ + ce0 + j)*H_ + gh0)*W_ + c8;
        *reinterpret_cast<float4*>(op)   = make_float4(v[0], v[1], v[2], v[3]);
        *reinterpret_cast<float4*>(op+4) = make_float4(v[4], v[5], v[6], v[7]);
    }
    #pragma unroll
    for (int off = 16; off; off >>= 1) {
        lsum += __shfl_down_sync(0xffffffffu, lsum, off);
        lsq  += __shfl_down_sync(0xffffffffu, lsq , off);
    }
    int wid = t >> 5, lane = t & 31;
    if (lane == 0) { red[wid] = lsum; red[wid+8] = lsq; }
    __syncthreads();
    if (t == 0) {
        float s = 0.f, q = 0.f;
        #pragma unroll
        for (int i = 0; i < 8; i++) { s += red[i]; q += red[i+8]; }
        atomicAdd(&g_stats[(b*C_+c)*2+0], s);
        atomicAdd(&g_stats[(b*C_+c)*2+1], q);
    }
}

// ---------------- k2: fold gate params ----------------
// gated(a) = a*(G0 + G1*tanh(A1*a + B1)) with sigmoid -> tanh identity
__global__ void k2_gate(const float* __restrict__ gn_w, const float* __restrict__ gn_b,
    const float* __restrict__ cw, const float* __restrict__ cb,
    const float* __restrict__ sw, const float* __restrict__ sb,
    const float* __restrict__ wadd_p)
{
    int t = threadIdx.x;
    if (t >= B_*C_) return;
    int c = t & (C_-1), cg = c & 7;
    float s = g_stats[t*2], q = g_stats[t*2+1];
    const float N = (float)(9*P_);
    float mean = s / N;
    float var  = fmaxf(q / N - mean*mean, 0.f);
    float inv  = 1.f / sqrtf(var + EPSF);
    float wadd = *wadd_p;
    float tc = cw[cg]*mean + cb[cg];
    float gC = 1.f / (1.f + __expf(-tc));
    float alpha = sw[cg]*gn_w[cg]*inv;
    float beta  = sw[cg]*(gn_b[cg] - mean*inv*gn_w[cg]) + sb[cg];
    float w2 = 1.f - wadd;
    g_gate[t*4+0] = wadd*gC + 0.5f*w2;  // G0
    g_gate[t*4+1] = 0.5f*w2;            // G1
    g_gate[t*4+2] = 0.5f*alpha;         // A1
    g_gate[t*4+3] = 0.5f*beta;          // B1
}

// ---------------- k2b: fold conv BN ----------------
__global__ void k2b_prep(const float* __restrict__ g, const float* __restrict__ bb,
                         const float* __restrict__ m, const float* __restrict__ v)
{
    int idx = threadIdx.x;
    if (idx < OUP_) {
        float sc = g[idx] / sqrtf(v[idx] + EPSF);
        g_ep[idx*2]   = sc;
        g_ep[idx*2+1] = bb[idx] - m[idx]*sc;
    }
}

// ---------------- k3: tf32 mma.sync GEMM ----------------
static __device__ __forceinline__ uint32_t f2tf32(float x) {
    uint32_t r;
    asm("cvt.rna.tf32.f32 %0, %1;" : "=r"(r) : "f"(x));
    return r;
}
static __device__ __forceinline__ float tanhfast(float x) {
    float y;
    asm("tanh.approx.f32 %0, %1;" : "=f"(y) : "f"(x));
    return y;
}
#define MMA_TF32(ac, aa, bb) \
    asm volatile("mma.sync.aligned.m16n8k8.row.col.f32.tf32.tf32.f32 " \
        "{%0,%1,%2,%3}, {%4,%5,%6,%7}, {%8,%9}, {%0,%1,%2,%3};" \
        : "+f"(ac[0]), "+f"(ac[1]), "+f"(ac[2]), "+f"(ac[3]) \
        : "r"(aa[0]), "r"(aa[1]), "r"(aa[2]), "r"(aa[3]), "r"(bb[0]), "r"(bb[1]))

// smem stage: A[128m][16k] stride 20, B[256n][16k] stride 20, k-col swizzled
#define AW_ (128*20)
#define BW_ (256*20)
#define STG_ (AW_ + BW_)
#define SMEM_DYN (2*STG_*4)

__global__ __launch_bounds__(256) void k3_mma(const float* __restrict__ conv_w,
                                              float* __restrict__ out)
{
    extern __shared__ float sm[];
    __shared__ float s_gp[256];
    int t = threadIdx.x, lane = t & 31;
    int warp = t >> 5;
    int g = lane >> 2, tc = lane & 3;
    int m_base = (warp >> 2) * 64;
    int n_base = (warp & 3) * 64;
    int b = blockIdx.y, pos0 = blockIdx.x * 256;

    s_gp[t] = g_gate[b*256 + t];
    const float* aB = g_a + (size_t)b*CE_*P_ + pos0;

    float acc[4][8][4];
    #pragma unroll
    for (int i = 0; i < 4; i++)
        #pragma unroll
        for (int j = 0; j < 8; j++)
            #pragma unroll
            for (int k = 0; k < 4; k++) acc[i][j][k] = 0.f;

    float4 wreg[2];
    float breg[16];
    int swz = (t >> 3) & 3, low = t & 3;

    // prologue: chunk 0
    #pragma unroll
    for (int i = 0; i < 2; i++) {
        int idx = t + i*256;
        wreg[i] = *reinterpret_cast<const float4*>(conv_w + (idx>>2)*576 + (idx&3)*4);
    }
    #pragma unroll
    for (int kk = 0; kk < 16; kk++)
        breg[kk] = aB[(size_t)kk*P_ + t];
    __syncthreads();  // s_gp ready
    {
        float* As = sm; float* Bs = sm + AW_;
        #pragma unroll
        for (int i = 0; i < 2; i++) {
            int idx = t + i*256, o = idx>>2, kq = idx&3;
            float4 w = wreg[i];
            uint32_t c0=f2tf32(w.x), c1=f2tf32(w.y), c2=f2tf32(w.z), c3=f2tf32(w.w);
            float4* dst = reinterpret_cast<float4*>(As + o*20 + kq*4);
            *dst = make_float4(__uint_as_float(c0), __uint_as_float(c1),
                               __uint_as_float(c2), __uint_as_float(c3));
        }
        #pragma unroll
        for (int kk = 0; kk < 16; kk++) {
            int c = kk / 9;
            float a_ = breg[kk];
            float th = tanhfast(fmaf(s_gp[c*4+2], a_, s_gp[c*4+3]));
            float v = a_ * fmaf(s_gp[c*4+1], th, s_gp[c*4+0]);
            Bs[t*20 + ((((kk>>2)^swz)<<2) | ((kk&3)^low))] = __uint_as_float(f2tf32(v));
        }
    }
    __syncthreads();

    for (int kc = 0; kc < 36; kc++) {
        if (kc < 35) {
            int k0 = (kc+1)*16;
            #pragma unroll
            for (int i = 0; i < 2; i++) {
                int idx = t + i*256;
                wreg[i] = *reinterpret_cast<const float4*>(conv_w + (idx>>2)*576 + k0 + (idx&3)*4);
            }
            #pragma unroll
            for (int kk = 0; kk < 16; kk++)
                breg[kk] = aB[(size_t)(k0+kk)*P_ + t];
        }
        // MMA on current buffer
        {
            const float* As = sm + (kc&1)*STG_;
            const float* Bs = As + AW_;
            #pragma unroll
            for (int s = 0; s < 2; s++) {
                uint32_t afr[4][4], bfr[8][2];
                #pragma unroll
                for (int fm = 0; fm < 4; fm++) {
                    const float* pa = As + (m_base + 16*fm + g)*20 + s*8 + tc;
                    afr[fm][0] = __float_as_uint(pa[0]);
                    afr[fm][1] = __float_as_uint(pa[160]);
                    afr[fm][2] = __float_as_uint(pa[4]);
                    afr[fm][3] = __float_as_uint(pa[164]);
                }
                #pragma unroll
                for (int fn = 0; fn < 8; fn++) {
                    const float* pb = Bs + (n_base + 8*fn + g)*20 + (tc ^ (g & 3));
                    int q = fn & 3;
                    bfr[fn][0] = __float_as_uint(pb[((2*s  )^q)<<2]);
                    bfr[fn][1] = __float_as_uint(pb[((2*s+1)^q)<<2]);
                }
                #pragma unroll
                for (int fm = 0; fm < 4; fm++)
                    #pragma unroll
                    for (int fn = 0; fn < 8; fn++)
                        MMA_TF32(acc[fm][fn], afr[fm], bfr[fn]);
            }
        }
        // store next chunk into other buffer
        if (kc < 35) {
            float* As = sm + ((kc+1)&1)*STG_;
            float* Bs = As + AW_;
            #pragma unroll
            for (int i = 0; i < 2; i++) {
                int idx = t + i*256, o = idx>>2, kq = idx&3;
                float4 w = wreg[i];
                uint32_t c0=f2tf32(w.x), c1=f2tf32(w.y), c2=f2tf32(w.z), c3=f2tf32(w.w);
                float4* dst = reinterpret_cast<float4*>(As + o*20 + kq*4);
                *dst = make_float4(__uint_as_float(c0), __uint_as_float(c1),
                                   __uint_as_float(c2), __uint_as_float(c3));
            }
            int kb = (kc+1)*16;
            #pragma unroll
            for (int kk = 0; kk < 16; kk++) {
                int c = (kb + kk) / 9;
                float a_ = breg[kk];
                float th = tanhfast(fmaf(s_gp[c*4+2], a_, s_gp[c*4+3]));
                float v = a_ * fmaf(s_gp[c*4+1], th, s_gp[c*4+0]);
                Bs[t*20 + ((((kk>>2)^swz)<<2) | ((kk&3)^low))] = __uint_as_float(f2tf32(v));
            }
        }
        __syncthreads();
    }

    // epilogue: BN + SiLU + store
    #pragma unroll
    for (int fm = 0; fm < 4; fm++) {
        int r0 = m_base + 16*fm + g, r1 = r0 + 8;
        float sc0 = g_ep[r0*2], sh0 = g_ep[r0*2+1];
        float sc1 = g_ep[r1*2], sh1 = g_ep[r1*2+1];
        float* o0 = out + ((size_t)b*OUP_ + r0)*P_ + pos0 + n_base + 2*tc;
        float* o1 = out + ((size_t)b*OUP_ + r1)*P_ + pos0 + n_base + 2*tc;
        #pragma unroll
        for (int fn = 0; fn < 8; fn++) {
            float z0 = fmaf(acc[fm][fn][0], sc0, sh0);
            float z1 = fmaf(acc[fm][fn][1], sc0, sh0);
            float z2 = fmaf(acc[fm][fn][2], sc1, sh1);
            float z3 = fmaf(acc[fm][fn][3], sc1, sh1);
            float2 v0 = make_float2(z0/(1.f+__expf(-z0)), z1/(1.f+__expf(-z1)));
            float2 v1 = make_float2(z2/(1.f+__expf(-z2)), z3/(1.f+__expf(-z3)));
            *reinterpret_cast<float2*>(o0 + 8*fn) = v0;
            *reinterpret_cast<float2*>(o1 + 8*fn) = v1;
        }
    }
}

extern "C" void kernel_launch(void* const* d_in, const int* in_sizes, int n_in,
                              void* d_out, int out_size)
{
    const float* x      = (const float*)d_in[0];
    const float* gen_w  = (const float*)d_in[1];
    const float* bg     = (const float*)d_in[2];
    const float* bb     = (const float*)d_in[3];
    const float* bm     = (const float*)d_in[4];
    const float* bv     = (const float*)d_in[5];
    const float* gn_w   = (const float*)d_in[6];
    const float* gn_b   = (const float*)d_in[7];
    const float* cw     = (const float*)d_in[8];
    const float* cb     = (const float*)d_in[9];
    const float* sw     = (const float*)d_in[10];
    const float* sb     = (const float*)d_in[11];
    const float* wadd   = (const float*)d_in[12];
    const float* conv_w = (const float*)d_in[13];
    const float* cbg    = (const float*)d_in[14];
    const float* cbb    = (const float*)d_in[15];
    const float* cbm    = (const float*)d_in[16];
    const float* cbv    = (const float*)d_in[17];
    float* out = (float*)d_out;

    cudaFuncSetAttribute(k3_mma, cudaFuncAttributeMaxDynamicSharedMemorySize, SMEM_DYN);

    k0_zero<<<1, 1024>>>();
    k1_gen<<<dim3(8, C_, B_), 256>>>(x, gen_w, bg, bb, bm, bv);
    k2_gate<<<1, 512>>>(gn_w, gn_b, cw, cb, sw, sb, wadd);
    k2b_prep<<<1, 128>>>(cbg, cbb, cbm, cbv);
    k3_mma<<<dim3(P_/256, B_), 256, SMEM_DYN>>>(conv_w, out);
}

// round 4
// speedup vs baseline: 1.8169x; 1.3060x over previous
#include <cuda_runtime.h>
#include <cuda_fp16.h>
#include <cstdint>

#define B_   8
#define C_   64
#define H_   128
#define W_   128
#define CE_  576
#define P_   (H_*W_)
#define OUP_ 128
#define EPSF 1e-5f

// ---- scratch (device globals; no runtime allocation allowed) ----
__device__ __half g_ah[(size_t)B_*CE_*P_];  // 151 MB: relu(bn(dwconv)) fp16  [b][k][p]
__device__ float g_stats[B_*C_*2];          // sum, sumsq per (b,c)
__device__ float g_gate[B_*C_*4];           // G0, G1, A1, B1 per (b,c)
__device__ float g_ep[OUP_*2];              // conv BN folded: scale, shift per o

// ---------------- k0: zero stats ----------------
__global__ void k0_zero() { g_stats[threadIdx.x] = 0.f; }

// ---------------- k1: depthwise conv + BN + ReLU + fp16 store + stats ----------------
__global__ __launch_bounds__(256) void k1_gen(
    const float* __restrict__ x,  const float* __restrict__ gw,
    const float* __restrict__ bg, const float* __restrict__ bb,
    const float* __restrict__ bm, const float* __restrict__ bv)
{
    int t = threadIdx.x;
    int rowblk = blockIdx.x, c = blockIdx.y, b = blockIdx.z;
    __shared__ float sx[18*130];
    __shared__ float swv[81], ssc[9], ssh[9];
    __shared__ float red[16];

    const float* xp = x + (size_t)(b*C_ + c)*P_;
    for (int idx = t; idx < 18*130; idx += 256) {
        int rr = idx / 130, cc = idx - rr*130;
        int gh = rowblk*16 + rr - 1, gwc = cc - 1;
        float v = 0.f;
        if ((unsigned)gh < (unsigned)H_ && (unsigned)gwc < (unsigned)W_)
            v = xp[gh*W_ + gwc];
        sx[idx] = v;
    }
    int ce0 = c*9;
    if (t < 81) swv[t] = gw[ce0*9 + t];
    if (t < 9) {
        float g = bg[ce0+t];
        float sc = g / sqrtf(bv[ce0+t] + EPSF);
        ssc[t] = sc;
        ssh[t] = bb[ce0+t] - bm[ce0+t]*sc;
    }
    __syncthreads();

    int r = t >> 4, c8 = (t & 15) * 8;
    float xs0[10], xs1[10], xs2[10];
    #pragma unroll
    for (int i = 0; i < 10; i++) {
        xs0[i] = sx[(r  )*130 + c8 + i];
        xs1[i] = sx[(r+1)*130 + c8 + i];
        xs2[i] = sx[(r+2)*130 + c8 + i];
    }
    float lsum = 0.f, lsq = 0.f;
    int gh0 = rowblk*16 + r;
    #pragma unroll
    for (int j = 0; j < 9; j++) {
        float w0=swv[j*9+0], w1=swv[j*9+1], w2=swv[j*9+2];
        float w3=swv[j*9+3], w4=swv[j*9+4], w5=swv[j*9+5];
        float w6=swv[j*9+6], w7=swv[j*9+7], w8=swv[j*9+8];
        float sc = ssc[j], sh = ssh[j];
        float v[8];
        #pragma unroll
        for (int px = 0; px < 8; px++) {
            float acc = xs0[px]*w0;
            acc = fmaf(xs0[px+1], w1, acc);
            acc = fmaf(xs0[px+2], w2, acc);
            acc = fmaf(xs1[px  ], w3, acc);
            acc = fmaf(xs1[px+1], w4, acc);
            acc = fmaf(xs1[px+2], w5, acc);
            acc = fmaf(xs2[px  ], w6, acc);
            acc = fmaf(xs2[px+1], w7, acc);
            acc = fmaf(xs2[px+2], w8, acc);
            float av = fmaxf(fmaf(acc, sc, sh), 0.f);
            v[px] = av;
            lsum += av;
            lsq = fmaf(av, av, lsq);
        }
        __half2 h0 = __floats2half2_rn(v[0], v[1]);
        __half2 h1 = __floats2half2_rn(v[2], v[3]);
        __half2 h2 = __floats2half2_rn(v[4], v[5]);
        __half2 h3 = __floats2half2_rn(v[6], v[7]);
        uint4 u;
        u.x = *reinterpret_cast<unsigned*>(&h0);
        u.y = *reinterpret_cast<unsigned*>(&h1);
        u.z = *reinterpret_cast<unsigned*>(&h2);
        u.w = *reinterpret_cast<unsigned*>(&h3);
        __half* op = g_ah + ((size_t)(b*CE_ + ce0 + j)*H_ + gh0)*W_ + c8;
        *reinterpret_cast<uint4*>(op) = u;
    }
    #pragma unroll
    for (int off = 16; off; off >>= 1) {
        lsum += __shfl_down_sync(0xffffffffu, lsum, off);
        lsq  += __shfl_down_sync(0xffffffffu, lsq , off);
    }
    int wid = t >> 5, lane = t & 31;
    if (lane == 0) { red[wid] = lsum; red[wid+8] = lsq; }
    __syncthreads();
    if (t == 0) {
        float s = 0.f, q = 0.f;
        #pragma unroll
        for (int i = 0; i < 8; i++) { s += red[i]; q += red[i+8]; }
        atomicAdd(&g_stats[(b*C_+c)*2+0], s);
        atomicAdd(&g_stats[(b*C_+c)*2+1], q);
    }
}

// ---------------- k2: fold gate params (tanh form) ----------------
__global__ void k2_gate(const float* __restrict__ gn_w, const float* __restrict__ gn_b,
    const float* __restrict__ cw, const float* __restrict__ cb,
    const float* __restrict__ sw, const float* __restrict__ sb,
    const float* __restrict__ wadd_p)
{
    int t = threadIdx.x;
    if (t >= B_*C_) return;
    int c = t & (C_-1), cg = c & 7;
    float s = g_stats[t*2], q = g_stats[t*2+1];
    const float N = (float)(9*P_);
    float mean = s / N;
    float var  = fmaxf(q / N - mean*mean, 0.f);
    float inv  = 1.f / sqrtf(var + EPSF);
    float wadd = *wadd_p;
    float tc = cw[cg]*mean + cb[cg];
    float gC = 1.f / (1.f + __expf(-tc));
    float alpha = sw[cg]*gn_w[cg]*inv;
    float beta  = sw[cg]*(gn_b[cg] - mean*inv*gn_w[cg]) + sb[cg];
    float w2 = 1.f - wadd;
    g_gate[t*4+0] = wadd*gC + 0.5f*w2;  // G0
    g_gate[t*4+1] = 0.5f*w2;            // G1
    g_gate[t*4+2] = 0.5f*alpha;         // A1
    g_gate[t*4+3] = 0.5f*beta;          // B1
}

// ---------------- k2b: fold conv BN ----------------
__global__ void k2b_prep(const float* __restrict__ g, const float* __restrict__ bb,
                         const float* __restrict__ m, const float* __restrict__ v)
{
    int idx = threadIdx.x;
    if (idx < OUP_) {
        float sc = g[idx] / sqrtf(v[idx] + EPSF);
        g_ep[idx*2]   = sc;
        g_ep[idx*2+1] = bb[idx] - m[idx]*sc;
    }
}

// ---------------- k3: fp16 mma.sync GEMM with ldmatrix ----------------
static __device__ __forceinline__ float tanhfast(float x) {
    float y;
    asm("tanh.approx.f32 %0, %1;" : "=f"(y) : "f"(x));
    return y;
}
#define LDSM4(r0,r1,r2,r3,addr) \
    asm volatile("ldmatrix.sync.aligned.m8n8.x4.shared.b16 {%0,%1,%2,%3}, [%4];" \
        : "=r"(r0),"=r"(r1),"=r"(r2),"=r"(r3) : "r"(addr))
#define MMA16816(c, a, b) \
    asm volatile("mma.sync.aligned.m16n8k16.row.col.f32.f16.f16.f32 " \
        "{%0,%1,%2,%3}, {%4,%5,%6,%7}, {%8,%9}, {%0,%1,%2,%3};" \
        : "+f"(c[0]),"+f"(c[1]),"+f"(c[2]),"+f"(c[3]) \
        : "r"(a[0]),"r"(a[1]),"r"(a[2]),"r"(a[3]), "r"(b[0]),"r"(b[1]))

// swizzled byte offset: row stride 32B (16 halves), 16B half selected by sel
static __device__ __forceinline__ uint32_t swoff(int row, int sel) {
    return (uint32_t)(row*32 + ((sel<<4) ^ ((row & 4) << 2)));
}

__global__ __launch_bounds__(256) void k3_mma(const float* __restrict__ conv_w,
                                              float* __restrict__ out)
{
    __shared__ __align__(16) __half sW[2][2048];   // [stage][128m x 16k]
    __shared__ __align__(16) __half sB[2][4096];   // [stage][256n x 16k]
    __shared__ __align__(16) float s_gp[256];

    int t = threadIdx.x, lane = t & 31, warp = t >> 5;
    int m_base = (warp >> 2) * 64;
    int n_base = (warp & 3) * 64;
    int b = blockIdx.y, pos0 = blockIdx.x * 256;

    s_gp[t] = g_gate[b*256 + t];
    const __half* aB = g_ah + (size_t)b*CE_*P_ + pos0 + t;

    float acc[4][8][4];
    #pragma unroll
    for (int i = 0; i < 4; i++)
        #pragma unroll
        for (int j = 0; j < 8; j++)
            #pragma unroll
            for (int k = 0; k < 4; k++) acc[i][j][k] = 0.f;

    uint32_t baseW = (uint32_t)__cvta_generic_to_shared(&sW[0][0]);
    uint32_t baseB = (uint32_t)__cvta_generic_to_shared(&sB[0][0]);
    // ldmatrix per-lane offsets
    int mA = m_base + (lane & 15);
    uint32_t offA = swoff(mA, lane >> 4);
    int nB = n_base + ((lane >> 4) << 3) + (lane & 7);
    uint32_t offB = swoff(nB, (lane >> 3) & 1);
    // producer store offsets
    int wo = t >> 1, wsel = t & 1;
    uint32_t wst = swoff(wo, wsel);
    uint32_t bst0 = swoff(t, 0), bst1 = swoff(t, 1);
    const float* wpB = conv_w + wo*576 + wsel*8;

    // ---- prologue: produce chunk 0 into stage 0 ----
    {
        float4 w0 = *reinterpret_cast<const float4*>(wpB);
        float4 w1 = *reinterpret_cast<const float4*>(wpB + 4);
        __half hb[16];
        #pragma unroll
        for (int kk = 0; kk < 16; kk++) hb[kk] = aB[(size_t)kk*P_];
        __syncthreads();  // s_gp ready
        __half2 hw[4];
        hw[0] = __floats2half2_rn(w0.x, w0.y); hw[1] = __floats2half2_rn(w0.z, w0.w);
        hw[2] = __floats2half2_rn(w1.x, w1.y); hw[3] = __floats2half2_rn(w1.z, w1.w);
        *reinterpret_cast<uint4*>(reinterpret_cast<char*>(&sW[0][0]) + wst) =
            *reinterpret_cast<uint4*>(hw);
        float v[16];
        #pragma unroll
        for (int kk = 0; kk < 16; kk++) {
            int c = kk / 9;
            float4 gp = reinterpret_cast<const float4*>(s_gp)[c];
            float a_ = __half2float(hb[kk]);
            float th = tanhfast(fmaf(gp.z, a_, gp.w));
            v[kk] = a_ * fmaf(gp.y, th, gp.x);
        }
        __half2 hv[8];
        #pragma unroll
        for (int q = 0; q < 8; q++) hv[q] = __floats2half2_rn(v[2*q], v[2*q+1]);
        *reinterpret_cast<uint4*>(reinterpret_cast<char*>(&sB[0][0]) + bst0) =
            *reinterpret_cast<uint4*>(&hv[0]);
        *reinterpret_cast<uint4*>(reinterpret_cast<char*>(&sB[0][0]) + bst1) =
            *reinterpret_cast<uint4*>(&hv[4]);
    }
    __syncthreads();

    for (int kc = 0; kc < 36; kc++) {
        int cur = kc & 1, nxt = cur ^ 1;
        // prefetch next chunk into registers
        float4 w0, w1;
        __half hb[16];
        if (kc < 35) {
            int k0 = (kc+1)*16;
            w0 = *reinterpret_cast<const float4*>(wpB + k0);
            w1 = *reinterpret_cast<const float4*>(wpB + k0 + 4);
            #pragma unroll
            for (int kk = 0; kk < 16; kk++) hb[kk] = aB[(size_t)(k0+kk)*P_];
        }
        // MMA on current stage
        {
            uint32_t aW = baseW + cur*4096 + offA;
            uint32_t aBs = baseB + cur*8192 + offB;
            uint32_t afr[4][4], bfr[8][2];
            #pragma unroll
            for (int fm = 0; fm < 4; fm++)
                LDSM4(afr[fm][0], afr[fm][1], afr[fm][2], afr[fm][3], aW + fm*512);
            #pragma unroll
            for (int pr = 0; pr < 4; pr++) {
                uint32_t r0, r1, r2, r3;
                LDSM4(r0, r1, r2, r3, aBs + pr*512);
                bfr[2*pr][0] = r0; bfr[2*pr][1] = r1;
                bfr[2*pr+1][0] = r2; bfr[2*pr+1][1] = r3;
            }
            #pragma unroll
            for (int fm = 0; fm < 4; fm++)
                #pragma unroll
                for (int fn = 0; fn < 8; fn++)
                    MMA16816(acc[fm][fn], afr[fm], bfr[fn]);
        }
        // gate + store next chunk
        if (kc < 35) {
            int k0 = (kc+1)*16;
            __half2 hw[4];
            hw[0] = __floats2half2_rn(w0.x, w0.y); hw[1] = __floats2half2_rn(w0.z, w0.w);
            hw[2] = __floats2half2_rn(w1.x, w1.y); hw[3] = __floats2half2_rn(w1.z, w1.w);
            *reinterpret_cast<uint4*>(reinterpret_cast<char*>(&sW[0][0]) + nxt*4096 + wst) =
                *reinterpret_cast<uint4*>(hw);
            float v[16];
            #pragma unroll
            for (int kk = 0; kk < 16; kk++) {
                int c = (k0 + kk) / 9;
                float4 gp = reinterpret_cast<const float4*>(s_gp)[c];
                float a_ = __half2float(hb[kk]);
                float th = tanhfast(fmaf(gp.z, a_, gp.w));
                v[kk] = a_ * fmaf(gp.y, th, gp.x);
            }
            __half2 hv[8];
            #pragma unroll
            for (int q = 0; q < 8; q++) hv[q] = __floats2half2_rn(v[2*q], v[2*q+1]);
            *reinterpret_cast<uint4*>(reinterpret_cast<char*>(&sB[0][0]) + nxt*8192 + bst0) =
                *reinterpret_cast<uint4*>(&hv[0]);
            *reinterpret_cast<uint4*>(reinterpret_cast<char*>(&sB[0][0]) + nxt*8192 + bst1) =
                *reinterpret_cast<uint4*>(&hv[4]);
        }
        __syncthreads();
    }

    // epilogue: BN + SiLU + store
    int g = lane >> 2, tc4 = lane & 3;
    #pragma unroll
    for (int fm = 0; fm < 4; fm++) {
        int r0 = m_base + 16*fm + g, r1 = r0 + 8;
        float sc0 = g_ep[r0*2], sh0 = g_ep[r0*2+1];
        float sc1 = g_ep[r1*2], sh1 = g_ep[r1*2+1];
        float* o0 = out + ((size_t)b*OUP_ + r0)*P_ + pos0 + n_base + 2*tc4;
        float* o1 = out + ((size_t)b*OUP_ + r1)*P_ + pos0 + n_base + 2*tc4;
        #pragma unroll
        for (int fn = 0; fn < 8; fn++) {
            float z0 = fmaf(acc[fm][fn][0], sc0, sh0);
            float z1 = fmaf(acc[fm][fn][1], sc0, sh0);
            float z2 = fmaf(acc[fm][fn][2], sc1, sh1);
            float z3 = fmaf(acc[fm][fn][3], sc1, sh1);
            float2 v0 = make_float2(z0/(1.f+__expf(-z0)), z1/(1.f+__expf(-z1)));
            float2 v1 = make_float2(z2/(1.f+__expf(-z2)), z3/(1.f+__expf(-z3)));
            *reinterpret_cast<float2*>(o0 + 8*fn) = v0;
            *reinterpret_cast<float2*>(o1 + 8*fn) = v1;
        }
    }
}

extern "C" void kernel_launch(void* const* d_in, const int* in_sizes, int n_in,
                              void* d_out, int out_size)
{
    const float* x      = (const float*)d_in[0];
    const float* gen_w  = (const float*)d_in[1];
    const float* bg     = (const float*)d_in[2];
    const float* bb     = (const float*)d_in[3];
    const float* bm     = (const float*)d_in[4];
    const float* bv     = (const float*)d_in[5];
    const float* gn_w   = (const float*)d_in[6];
    const float* gn_b   = (const float*)d_in[7];
    const float* cw     = (const float*)d_in[8];
    const float* cb     = (const float*)d_in[9];
    const float* sw     = (const float*)d_in[10];
    const float* sb     = (const float*)d_in[11];
    const float* wadd   = (const float*)d_in[12];
    const float* conv_w = (const float*)d_in[13];
    const float* cbg    = (const float*)d_in[14];
    const float* cbb    = (const float*)d_in[15];
    const float* cbm    = (const float*)d_in[16];
    const float* cbv    = (const float*)d_in[17];
    float* out = (float*)d_out;

    k0_zero<<<1, 1024>>>();
    k1_gen<<<dim3(8, C_, B_), 256>>>(x, gen_w, bg, bb, bm, bv);
    k2_gate<<<1, 512>>>(gn_w, gn_b, cw, cb, sw, sb, wadd);
    k2b_prep<<<1, 128>>>(cbg, cbb, cbm, cbv);
    k3_mma<<<dim3(P_/256, B_), 256>>>(conv_w, out);
}

// round 5
// speedup vs baseline: 2.1619x; 1.1899x over previous
#include <cuda_runtime.h>
#include <cuda_fp16.h>
#include <cstdint>

#define B_   8
#define C_   64
#define H_   128
#define W_   128
#define CE_  576
#define P_   (H_*W_)
#define OUP_ 128
#define EPSF 1e-5f

// ---- scratch (device globals; no runtime allocation allowed) ----
__device__ __half g_ah[(size_t)B_*CE_*P_];  // 151 MB: relu(bn(dwconv)) fp16  [b][k][p]
__device__ __half g_wh[CE_*OUP_];           // fp16 weights, chunk-major [36][128 o][16 k]
__device__ float g_stats[B_*C_*2];          // sum, sumsq per (b,c)
__device__ float g_gate[B_*C_*4];           // G0, G1, A1, B1 per (b,c)
__device__ float g_ep[OUP_*2];              // conv BN folded: scale, shift per o

// ---------------- k0: zero stats ----------------
__global__ void k0_zero() { g_stats[threadIdx.x] = 0.f; }

// ---------------- k1: depthwise conv + BN + ReLU + fp16 store + stats ----------------
__global__ __launch_bounds__(256) void k1_gen(
    const float* __restrict__ x,  const float* __restrict__ gw,
    const float* __restrict__ bg, const float* __restrict__ bb,
    const float* __restrict__ bm, const float* __restrict__ bv)
{
    int t = threadIdx.x;
    int rowblk = blockIdx.x, c = blockIdx.y, b = blockIdx.z;
    __shared__ float sx[18*130];
    __shared__ float swv[81], ssc[9], ssh[9];
    __shared__ float red[16];

    const float* xp = x + (size_t)(b*C_ + c)*P_;
    for (int idx = t; idx < 18*130; idx += 256) {
        int rr = idx / 130, cc = idx - rr*130;
        int gh = rowblk*16 + rr - 1, gwc = cc - 1;
        float v = 0.f;
        if ((unsigned)gh < (unsigned)H_ && (unsigned)gwc < (unsigned)W_)
            v = xp[gh*W_ + gwc];
        sx[idx] = v;
    }
    int ce0 = c*9;
    if (t < 81) swv[t] = gw[ce0*9 + t];
    if (t < 9) {
        float g = bg[ce0+t];
        float sc = g / sqrtf(bv[ce0+t] + EPSF);
        ssc[t] = sc;
        ssh[t] = bb[ce0+t] - bm[ce0+t]*sc;
    }
    __syncthreads();

    int r = t >> 4, c8 = (t & 15) * 8;
    float xs0[10], xs1[10], xs2[10];
    #pragma unroll
    for (int i = 0; i < 10; i++) {
        xs0[i] = sx[(r  )*130 + c8 + i];
        xs1[i] = sx[(r+1)*130 + c8 + i];
        xs2[i] = sx[(r+2)*130 + c8 + i];
    }
    float lsum = 0.f, lsq = 0.f;
    int gh0 = rowblk*16 + r;
    #pragma unroll
    for (int j = 0; j < 9; j++) {
        float w0=swv[j*9+0], w1=swv[j*9+1], w2=swv[j*9+2];
        float w3=swv[j*9+3], w4=swv[j*9+4], w5=swv[j*9+5];
        float w6=swv[j*9+6], w7=swv[j*9+7], w8=swv[j*9+8];
        float sc = ssc[j], sh = ssh[j];
        float v[8];
        #pragma unroll
        for (int px = 0; px < 8; px++) {
            float acc = xs0[px]*w0;
            acc = fmaf(xs0[px+1], w1, acc);
            acc = fmaf(xs0[px+2], w2, acc);
            acc = fmaf(xs1[px  ], w3, acc);
            acc = fmaf(xs1[px+1], w4, acc);
            acc = fmaf(xs1[px+2], w5, acc);
            acc = fmaf(xs2[px  ], w6, acc);
            acc = fmaf(xs2[px+1], w7, acc);
            acc = fmaf(xs2[px+2], w8, acc);
            float av = fmaxf(fmaf(acc, sc, sh), 0.f);
            v[px] = av;
            lsum += av;
            lsq = fmaf(av, av, lsq);
        }
        __half2 h0 = __floats2half2_rn(v[0], v[1]);
        __half2 h1 = __floats2half2_rn(v[2], v[3]);
        __half2 h2 = __floats2half2_rn(v[4], v[5]);
        __half2 h3 = __floats2half2_rn(v[6], v[7]);
        uint4 u;
        u.x = *reinterpret_cast<unsigned*>(&h0);
        u.y = *reinterpret_cast<unsigned*>(&h1);
        u.z = *reinterpret_cast<unsigned*>(&h2);
        u.w = *reinterpret_cast<unsigned*>(&h3);
        __half* op = g_ah + ((size_t)(b*CE_ + ce0 + j)*H_ + gh0)*W_ + c8;
        *reinterpret_cast<uint4*>(op) = u;
    }
    #pragma unroll
    for (int off = 16; off; off >>= 1) {
        lsum += __shfl_down_sync(0xffffffffu, lsum, off);
        lsq  += __shfl_down_sync(0xffffffffu, lsq , off);
    }
    int wid = t >> 5, lane = t & 31;
    if (lane == 0) { red[wid] = lsum; red[wid+8] = lsq; }
    __syncthreads();
    if (t == 0) {
        float s = 0.f, q = 0.f;
        #pragma unroll
        for (int i = 0; i < 8; i++) { s += red[i]; q += red[i+8]; }
        atomicAdd(&g_stats[(b*C_+c)*2+0], s);
        atomicAdd(&g_stats[(b*C_+c)*2+1], q);
    }
}

// ---------------- k2: fold gate params (tanh form) ----------------
__global__ void k2_gate(const float* __restrict__ gn_w, const float* __restrict__ gn_b,
    const float* __restrict__ cw, const float* __restrict__ cb,
    const float* __restrict__ sw, const float* __restrict__ sb,
    const float* __restrict__ wadd_p)
{
    int t = threadIdx.x;
    if (t >= B_*C_) return;
    int c = t & (C_-1), cg = c & 7;
    float s = g_stats[t*2], q = g_stats[t*2+1];
    const float N = (float)(9*P_);
    float mean = s / N;
    float var  = fmaxf(q / N - mean*mean, 0.f);
    float inv  = 1.f / sqrtf(var + EPSF);
    float wadd = *wadd_p;
    float tc = cw[cg]*mean + cb[cg];
    float gC = 1.f / (1.f + __expf(-tc));
    float alpha = sw[cg]*gn_w[cg]*inv;
    float beta  = sw[cg]*(gn_b[cg] - mean*inv*gn_w[cg]) + sb[cg];
    float w2 = 1.f - wadd;
    g_gate[t*4+0] = wadd*gC + 0.5f*w2;  // G0
    g_gate[t*4+1] = 0.5f*w2;            // G1
    g_gate[t*4+2] = 0.5f*alpha;         // A1
    g_gate[t*4+3] = 0.5f*beta;          // B1
}

// ---------------- k2b: convert W to fp16 chunk-major + fold conv BN ----------------
__global__ void k2b_prep(const float* __restrict__ cwv,
                         const float* __restrict__ g, const float* __restrict__ bb,
                         const float* __restrict__ m, const float* __restrict__ v)
{
    int idx = blockIdx.x*256 + threadIdx.x;
    if (idx < CE_*OUP_) {
        int o = idx / CE_, k = idx - o*CE_;
        // dst layout: [k>>4][o][k&15]
        g_wh[((size_t)(k >> 4)*OUP_ + o)*16 + (k & 15)] = __float2half_rn(cwv[idx]);
    }
    if (blockIdx.x == 0 && threadIdx.x < OUP_) {
        int i = threadIdx.x;
        float sc = g[i] / sqrtf(v[i] + EPSF);
        g_ep[i*2]   = sc;
        g_ep[i*2+1] = bb[i] - m[i]*sc;
    }
}

// ---------------- k3: fp16 mma.sync GEMM, vectorized loads + ldmatrix(.trans) ----------------
static __device__ __forceinline__ float tanhfast(float x) {
    float y;
    asm("tanh.approx.f32 %0, %1;" : "=f"(y) : "f"(x));
    return y;
}
#define LDSM4(r0,r1,r2,r3,addr) \
    asm volatile("ldmatrix.sync.aligned.m8n8.x4.shared.b16 {%0,%1,%2,%3}, [%4];" \
        : "=r"(r0),"=r"(r1),"=r"(r2),"=r"(r3) : "r"(addr))
#define LDSM4T(r0,r1,r2,r3,addr) \
    asm volatile("ldmatrix.sync.aligned.m8n8.x4.trans.shared.b16 {%0,%1,%2,%3}, [%4];" \
        : "=r"(r0),"=r"(r1),"=r"(r2),"=r"(r3) : "r"(addr))
#define MMA16816(c, a, b) \
    asm volatile("mma.sync.aligned.m16n8k16.row.col.f32.f16.f16.f32 " \
        "{%0,%1,%2,%3}, {%4,%5,%6,%7}, {%8,%9}, {%0,%1,%2,%3};" \
        : "+f"(c[0]),"+f"(c[1]),"+f"(c[2]),"+f"(c[3]) \
        : "r"(a[0]),"r"(a[1]),"r"(a[2]),"r"(a[3]), "r"(b[0]),"r"(b[1]))

// W smem: [128 m][16 k], 32B rows, 16B-half select swizzle
static __device__ __forceinline__ uint32_t swoff(int row, int sel) {
    return (uint32_t)(row*32 + ((sel<<4) ^ ((row & 4) << 2)));
}
// gate transform on 8 packed halves (fp32 math)
static __device__ __forceinline__ uint4 gate8(uint4 u, float4 gp) {
    __half2* h = reinterpret_cast<__half2*>(&u);
    #pragma unroll
    for (int i = 0; i < 4; i++) {
        float2 f = __half22float2(h[i]);
        float th0 = tanhfast(fmaf(gp.z, f.x, gp.w));
        float th1 = tanhfast(fmaf(gp.z, f.y, gp.w));
        h[i] = __floats2half2_rn(f.x * fmaf(gp.y, th0, gp.x),
                                 f.y * fmaf(gp.y, th1, gp.x));
    }
    return u;
}

__global__ __launch_bounds__(256) void k3_mma(float* __restrict__ out)
{
    __shared__ __align__(16) __half sW[2][2048];   // [stage][128m x 16k] swizzled
    __shared__ __align__(16) __half sB[2][4096];   // [stage][16k x 256pos] chunk-swizzled
    __shared__ __align__(16) float s_gp[256];

    int t = threadIdx.x, lane = t & 31, warp = t >> 5;
    int m_base = (warp >> 2) * 64;
    int n_base = (warp & 3) * 64;
    int b = blockIdx.y, pos0 = blockIdx.x * 256;

    s_gp[t] = g_gate[b*256 + t];
    const __half* aBase = g_ah + (size_t)b*CE_*P_ + pos0;

    float acc[4][8][4];
    #pragma unroll
    for (int i = 0; i < 4; i++)
        #pragma unroll
        for (int j = 0; j < 8; j++)
            #pragma unroll
            for (int k = 0; k < 4; k++) acc[i][j][k] = 0.f;

    uint32_t baseW = (uint32_t)__cvta_generic_to_shared(&sW[0][0]);
    uint32_t baseB = (uint32_t)__cvta_generic_to_shared(&sB[0][0]);

    // ldmatrix A offsets (non-trans, [m][k] rows)
    uint32_t offA = swoff(m_base + (lane & 15), lane >> 4);
    // ldmatrix B offsets (trans, [k][pos] rows of 512B, 16B chunk swizzle c^(k&7))
    int gq = lane >> 3, rq = lane & 7;
    int kL = (gq & 1)*8 + rq;
    uint32_t kL512 = (uint32_t)kL * 512;
    int kLm = kL & 7;
    int cB = (n_base >> 3) + (gq >> 1);
    // producer offsets
    int kb0 = t >> 5, ch0 = t & 31;     // pass0: k rows 0-7 (warp-uniform k)
    int kb1 = kb0 + 8;                   // pass1: k rows 8-15
    uint32_t bsm0 = (uint32_t)kb0*512 + (uint32_t)((ch0 ^ (kb0 & 7)) << 4);
    uint32_t bsm1 = (uint32_t)kb1*512 + (uint32_t)((ch0 ^ (kb1 & 7)) << 4);
    int wrow = t >> 1, wsel = t & 1;
    uint32_t wst = swoff(wrow, wsel);
    const __half* wPtr = g_wh + ((size_t)wrow*16) + wsel*8;

    // ---- prologue: chunk 0 ----
    {
        uint4 wv = *reinterpret_cast<const uint4*>(wPtr);
        uint4 b0 = *reinterpret_cast<const uint4*>(aBase + (size_t)kb0*P_ + ch0*8);
        uint4 b1 = *reinterpret_cast<const uint4*>(aBase + (size_t)kb1*P_ + ch0*8);
        __syncthreads();  // s_gp ready
        *reinterpret_cast<uint4*>(reinterpret_cast<char*>(&sW[0][0]) + wst) = wv;
        float4 gp0 = reinterpret_cast<const float4*>(s_gp)[kb0/9];
        float4 gp1 = reinterpret_cast<const float4*>(s_gp)[kb1/9];
        *reinterpret_cast<uint4*>(reinterpret_cast<char*>(&sB[0][0]) + bsm0) = gate8(b0, gp0);
        *reinterpret_cast<uint4*>(reinterpret_cast<char*>(&sB[0][0]) + bsm1) = gate8(b1, gp1);
    }
    __syncthreads();

    for (int kc = 0; kc < 36; kc++) {
        int cur = kc & 1, nxt = cur ^ 1;
        uint4 wv, b0, b1;
        if (kc < 35) {
            int k0 = (kc+1)*16;
            wv = *reinterpret_cast<const uint4*>(wPtr + (size_t)(kc+1)*OUP_*16);
            b0 = *reinterpret_cast<const uint4*>(aBase + (size_t)(k0+kb0)*P_ + ch0*8);
            b1 = *reinterpret_cast<const uint4*>(aBase + (size_t)(k0+kb1)*P_ + ch0*8);
        }
        // MMA on current stage
        {
            uint32_t aW = baseW + cur*4096 + offA;
            uint32_t aB2 = baseB + cur*8192;
            uint32_t afr[4][4], bfr[8][2];
            #pragma unroll
            for (int fm = 0; fm < 4; fm++)
                LDSM4(afr[fm][0], afr[fm][1], afr[fm][2], afr[fm][3], aW + fm*512);
            #pragma unroll
            for (int pr = 0; pr < 4; pr++) {
                uint32_t r0, r1, r2, r3;
                uint32_t off = kL512 + (uint32_t)((((cB + pr*2) ^ kLm)) << 4);
                LDSM4T(r0, r1, r2, r3, aB2 + off);
                bfr[2*pr][0] = r0; bfr[2*pr][1] = r1;
                bfr[2*pr+1][0] = r2; bfr[2*pr+1][1] = r3;
            }
            #pragma unroll
            for (int fm = 0; fm < 4; fm++)
                #pragma unroll
                for (int fn = 0; fn < 8; fn++)
                    MMA16816(acc[fm][fn], afr[fm], bfr[fn]);
        }
        // gate + store next chunk
        if (kc < 35) {
            int k0 = (kc+1)*16;
            *reinterpret_cast<uint4*>(reinterpret_cast<char*>(&sW[0][0]) + nxt*4096 + wst) = wv;
            float4 gp0 = reinterpret_cast<const float4*>(s_gp)[(k0+kb0)/9];
            float4 gp1 = reinterpret_cast<const float4*>(s_gp)[(k0+kb1)/9];
            *reinterpret_cast<uint4*>(reinterpret_cast<char*>(&sB[0][0]) + nxt*8192 + bsm0) =
                gate8(b0, gp0);
            *reinterpret_cast<uint4*>(reinterpret_cast<char*>(&sB[0][0]) + nxt*8192 + bsm1) =
                gate8(b1, gp1);
        }
        __syncthreads();
    }

    // epilogue: BN + SiLU + store
    int g = lane >> 2, tc4 = lane & 3;
    #pragma unroll
    for (int fm = 0; fm < 4; fm++) {
        int r0 = m_base + 16*fm + g, r1 = r0 + 8;
        float sc0 = g_ep[r0*2], sh0 = g_ep[r0*2+1];
        float sc1 = g_ep[r1*2], sh1 = g_ep[r1*2+1];
        float* o0 = out + ((size_t)b*OUP_ + r0)*P_ + pos0 + n_base + 2*tc4;
        float* o1 = out + ((size_t)b*OUP_ + r1)*P_ + pos0 + n_base + 2*tc4;
        #pragma unroll
        for (int fn = 0; fn < 8; fn++) {
            float z0 = fmaf(acc[fm][fn][0], sc0, sh0);
            float z1 = fmaf(acc[fm][fn][1], sc0, sh0);
            float z2 = fmaf(acc[fm][fn][2], sc1, sh1);
            float z3 = fmaf(acc[fm][fn][3], sc1, sh1);
            float2 v0 = make_float2(z0/(1.f+__expf(-z0)), z1/(1.f+__expf(-z1)));
            float2 v1 = make_float2(z2/(1.f+__expf(-z2)), z3/(1.f+__expf(-z3)));
            *reinterpret_cast<float2*>(o0 + 8*fn) = v0;
            *reinterpret_cast<float2*>(o1 + 8*fn) = v1;
        }
    }
}

extern "C" void kernel_launch(void* const* d_in, const int* in_sizes, int n_in,
                              void* d_out, int out_size)
{
    const float* x      = (const float*)d_in[0];
    const float* gen_w  = (const float*)d_in[1];
    const float* bg     = (const float*)d_in[2];
    const float* bb     = (const float*)d_in[3];
    const float* bm     = (const float*)d_in[4];
    const float* bv     = (const float*)d_in[5];
    const float* gn_w   = (const float*)d_in[6];
    const float* gn_b   = (const float*)d_in[7];
    const float* cw     = (const float*)d_in[8];
    const float* cb     = (const float*)d_in[9];
    const float* sw     = (const float*)d_in[10];
    const float* sb     = (const float*)d_in[11];
    const float* wadd   = (const float*)d_in[12];
    const float* conv_w = (const float*)d_in[13];
    const float* cbg    = (const float*)d_in[14];
    const float* cbb    = (const float*)d_in[15];
    const float* cbm    = (const float*)d_in[16];
    const float* cbv    = (const float*)d_in[17];
    float* out = (float*)d_out;

    k0_zero<<<1, 1024>>>();
    k1_gen<<<dim3(8, C_, B_), 256>>>(x, gen_w, bg, bb, bm, bv);
    k2_gate<<<1, 512>>>(gn_w, gn_b, cw, cb, sw, sb, wadd);
    k2b_prep<<<(CE_*OUP_ + 255)/256, 256>>>(conv_w, cbg, cbb, cbm, cbv);
    k3_mma<<<dim3(P_/256, B_), 256>>>(out);
}